// round 14
// baseline (speedup 1.0000x reference)
#include <cuda_runtime.h>
#include <cuda_bf16.h>
#include <cuda_fp16.h>
#include <cstdint>

#define Bsz 8
#define Nsq 512
#define DM_ 1024
#define Hh 16
#define DK 64

// ---------------- scratch (static device arrays; no allocation) --------------
__device__ float g_logb[(size_t)Bsz*Hh*Nsq*Nsq]; // (b,h,n,m) fp32
__device__ float g_boxf[Bsz*Nsq*8];               // cx,cy,w,h,logw,logh
// packed bf16x2 hi/lo projections (b,h,n,d): idx = ((bh*512+n)*64+d)/2
__device__ uint32_t g_qh[Bsz*Hh*Nsq*DK/2];
__device__ uint32_t g_ql[Bsz*Hh*Nsq*DK/2];
__device__ uint32_t g_kh[Bsz*Hh*Nsq*DK/2];
__device__ uint32_t g_kl[Bsz*Hh*Nsq*DK/2];
__device__ uint32_t g_vh[Bsz*Hh*Nsq*DK/2];
__device__ uint32_t g_vl[Bsz*Hh*Nsq*DK/2];
// pre-converted GEMM operands (bf16 hi/lo pairs, row = 512 uint32)
__device__ uint32_t g_inh[3u*4096*512];   // queries/keys/values
__device__ uint32_t g_inl[3u*4096*512];
__device__ uint32_t g_wh[4u*1024*512];    // Wq,Wk,Wv,Wo
__device__ uint32_t g_wl[4u*1024*512];
__device__ uint32_t g_oh[4096u*512];      // attention output (b,n,h*64)
__device__ uint32_t g_ol[4096u*512];

// ---------------- helpers ----------------------------------------------------
__device__ __forceinline__ uint32_t smem_u32(const void* p) {
    uint32_t a;
    asm("{ .reg .u64 t; cvta.to.shared.u64 t, %1; cvt.u32.u64 %0, t; }" : "=r"(a) : "l"(p));
    return a;
}

#define LDSM4(r, a) \
    asm volatile("ldmatrix.sync.aligned.m8n8.x4.shared.b16 {%0,%1,%2,%3}, [%4];" \
        : "=r"((r)[0]), "=r"((r)[1]), "=r"((r)[2]), "=r"((r)[3]) : "r"(a))
#define LDSM4T(r, a) \
    asm volatile("ldmatrix.sync.aligned.m8n8.x4.trans.shared.b16 {%0,%1,%2,%3}, [%4];" \
        : "=r"((r)[0]), "=r"((r)[1]), "=r"((r)[2]), "=r"((r)[3]) : "r"(a))

#define CP_ASYNC16(dst, src) \
    asm volatile("cp.async.cg.shared.global [%0], [%1], 16;" :: "r"(dst), "l"(src) : "memory")
#define CP_COMMIT() asm volatile("cp.async.commit_group;" ::: "memory")
#define CP_WAIT(n)  asm volatile("cp.async.wait_group %0;" :: "n"(n) : "memory")

__device__ __forceinline__ void mma16816(float* c, const uint32_t* a, const uint32_t* b) {
    asm volatile("mma.sync.aligned.m16n8k16.row.col.f32.bf16.bf16.f32 "
        "{%0,%1,%2,%3}, {%4,%5,%6,%7}, {%8,%9}, {%0,%1,%2,%3};"
        : "+f"(c[0]), "+f"(c[1]), "+f"(c[2]), "+f"(c[3])
        : "r"(a[0]), "r"(a[1]), "r"(a[2]), "r"(a[3]), "r"(b[0]), "r"(b[1]));
}
__device__ __forceinline__ void mma16816h(float* c, const uint32_t* a, const uint32_t* b) {
    asm volatile("mma.sync.aligned.m16n8k16.row.col.f32.f16.f16.f32 "
        "{%0,%1,%2,%3}, {%4,%5,%6,%7}, {%8,%9}, {%0,%1,%2,%3};"
        : "+f"(c[0]), "+f"(c[1]), "+f"(c[2]), "+f"(c[3])
        : "r"(a[0]), "r"(a[1]), "r"(a[2]), "r"(a[3]), "r"(b[0]), "r"(b[1]));
}

// split two floats into packed bf16x2 hi + bf16x2 lo (residual)
__device__ __forceinline__ void split2(float x, float y, uint32_t& hi, uint32_t& lo) {
    asm("cvt.rn.bf16x2.f32 %0, %1, %2;" : "=r"(hi) : "f"(y), "f"(x));
    float fx = __uint_as_float(hi << 16);
    float fy = __uint_as_float(hi & 0xffff0000u);
    asm("cvt.rn.bf16x2.f32 %0, %1, %2;" : "=r"(lo) : "f"(y - fy), "f"(x - fx));
}
// fp16 variant
__device__ __forceinline__ void split2h(float x, float y, uint32_t& hi, uint32_t& lo) {
    __half2 h = __floats2half2_rn(x, y);
    hi = *reinterpret_cast<uint32_t*>(&h);
    float2 f = __half22float2(h);
    __half2 l = __floats2half2_rn(x - f.x, y - f.y);
    lo = *reinterpret_cast<uint32_t*>(&l);
}

// ---------------- box feature precompute ------------------------------------
__global__ void boxfeat_kernel(const float* __restrict__ boxes) {
    int i = blockIdx.x * 256 + threadIdx.x;            // < B*N = 4096
    float4 bx = *(const float4*)(boxes + (size_t)i * 4);
    float cx = (bx.x + bx.z) * 0.5f;
    float cy = (bx.y + bx.w) * 0.5f;
    float w  = (bx.z - bx.x) + 1.0f;
    float h  = (bx.w - bx.y) + 1.0f;
    float* o = g_boxf + (size_t)i * 8;
    o[0] = cx; o[1] = cy; o[2] = w; o[3] = h;
    o[4] = __logf(w); o[5] = __logf(h);
}

// ---------------- fused f32 -> bf16 hi/lo conversion (all 7 tensors) ----------
__global__ void conv_all_kernel(const float* __restrict__ q, const float* __restrict__ k,
                                const float* __restrict__ v, const float* __restrict__ wq,
                                const float* __restrict__ wk, const float* __restrict__ wv,
                                const float* __restrict__ wo) {
    size_t i = (size_t)blockIdx.x * 256 + threadIdx.x;   // < 4194304 float4s
    const float* src;
    uint32_t *dh, *dl;
    size_t off;
    if (i < 3145728) {
        int sel = (int)(i >> 20);
        off = i & 1048575;
        src = (sel == 0) ? q : (sel == 1) ? k : v;
        dh = g_inh + (size_t)sel * 2097152;
        dl = g_inl + (size_t)sel * 2097152;
    } else {
        size_t j = i - 3145728;
        int sel = (int)(j >> 18);
        off = j & 262143;
        src = (sel == 0) ? wq : (sel == 1) ? wk : (sel == 2) ? wv : wo;
        dh = g_wh + (size_t)sel * 524288;
        dl = g_wl + (size_t)sel * 524288;
    }
    float4 x = *(const float4*)(src + off * 4);
    uint32_t h0, l0, h1, l1;
    split2(x.x, x.y, h0, l0);
    split2(x.z, x.w, h1, l1);
    *(uint2*)(dh + off * 2) = make_uint2(h0, h1);
    *(uint2*)(dl + off * 2) = make_uint2(l0, l1);
}

// ============ device bodies: GEMM tile and bias block =========================
static constexpr int STAGE_B = 4 * 128 * 64;          // 32768
static constexpr int FUSED_SMEM = 3 * STAGE_B;        // 98304 (>= bias's 78336)

// ---- GEMM 128x128 tile body (3-stage cp.async ring, swizzled 64B rows) ------
__device__ __forceinline__ void gemm_tile_body(
        int bx, int by, int bz, char* smem,
        const float* b0p, const float* b1p, const float* b2p,
        float* C0, int a_sel, int mode) {
    int z = bz;
    const uint32_t* Ah;
    const uint32_t* Al;
    if (a_sel) { Ah = g_oh; Al = g_ol; }
    else       { Ah = g_inh + (size_t)z * 2097152; Al = g_inl + (size_t)z * 2097152; }
    int wsel = a_sel ? 3 : z;
    const uint32_t* Wh = g_wh + (size_t)wsel * 524288;
    const uint32_t* Wl = g_wl + (size_t)wsel * 524288;
    const float* bias = (z == 0) ? b0p : (z == 1) ? b1p : b2p;

    uint32_t sbase = smem_u32(smem);
    int tid = threadIdx.x;
    int lane = tid & 31, wid = tid >> 5;
    int wm = wid & 3, wn = wid >> 2;
    int m0 = bx * 128, n0 = by * 128;

    const uint32_t* srcb[4];
    srcb[0] = Ah + (size_t)m0 * 512;
    srcb[1] = Al + (size_t)m0 * 512;
    srcb[2] = Wh + (size_t)n0 * 512;
    srcb[3] = Wl + (size_t)n0 * 512;

    int arow0 = wm * 32 + (lane & 15);
    uint32_t ahalf = (uint32_t)(lane >> 4);
    int brow0 = wn * 64 + (lane & 7) + ((lane >> 4) & 1) * 8;
    uint32_t bhalf = (uint32_t)((lane >> 3) & 1);

    float acc[2][8][4];
#pragma unroll
    for (int i = 0; i < 2; i++)
#pragma unroll
        for (int j = 0; j < 8; j++)
#pragma unroll
            for (int q = 0; q < 4; q++) acc[i][j][q] = 0.0f;

    // prologue: chunks 0 and 1
#pragma unroll
    for (int pc = 0; pc < 2; pc++) {
        uint32_t bb = sbase + (uint32_t)pc * STAGE_B;
        int k0 = pc * 16;
#pragma unroll
        for (int p = 0; p < 8; p++) {
            int mat = p >> 1;
            int id2 = tid + (p & 1) * 256;
            int row = id2 >> 2, seg = id2 & 3;
            uint32_t dst = bb + (uint32_t)mat * 8192 + (uint32_t)row * 64
                         + (uint32_t)((seg ^ ((row >> 1) & 3)) * 16);
            CP_ASYNC16(dst, srcb[mat] + (size_t)row * 512 + k0 + seg * 4);
        }
        CP_COMMIT();
    }

    for (int c = 0; c < 32; ++c) {
        if (c < 31) { CP_WAIT(1); } else { CP_WAIT(0); }
        __syncthreads();

        if (c + 2 < 32) {
            uint32_t bb = sbase + (uint32_t)((c + 2) % 3) * STAGE_B;
            int k0 = (c + 2) * 16;
#pragma unroll
            for (int p = 0; p < 8; p++) {
                int mat = p >> 1;
                int id2 = tid + (p & 1) * 256;
                int row = id2 >> 2, seg = id2 & 3;
                uint32_t dst = bb + (uint32_t)mat * 8192 + (uint32_t)row * 64
                             + (uint32_t)((seg ^ ((row >> 1) & 3)) * 16);
                CP_ASYNC16(dst, srcb[mat] + (size_t)row * 512 + k0 + seg * 4);
            }
            CP_COMMIT();
        }

        uint32_t base = sbase + (uint32_t)(c % 3) * STAGE_B;
#pragma unroll
        for (int k16 = 0; k16 < 2; k16++) {
            uint32_t ah[2][4], al[2][4];
#pragma unroll
            for (int mt = 0; mt < 2; mt++) {
                int ar = arow0 + mt * 16;
                uint32_t aseg = ((uint32_t)(k16 * 2) + ahalf) ^ ((uint32_t)(ar >> 1) & 3u);
                uint32_t ao = base + (uint32_t)ar * 64 + aseg * 16;
                LDSM4(ah[mt], ao);
                LDSM4(al[mt], ao + 8192);
            }
#pragma unroll
            for (int ntp = 0; ntp < 4; ntp++) {
                uint32_t bh[4], bl[4];
                int br = brow0 + ntp * 16;
                uint32_t bseg = ((uint32_t)(k16 * 2) + bhalf) ^ ((uint32_t)(br >> 1) & 3u);
                uint32_t bo = base + 16384 + (uint32_t)br * 64 + bseg * 16;
                LDSM4(bh, bo);
                LDSM4(bl, bo + 8192);
#pragma unroll
                for (int mt = 0; mt < 2; mt++) {
#pragma unroll
                    for (int h8 = 0; h8 < 2; h8++) {
                        float* cc = acc[mt][ntp * 2 + h8];
                        mma16816(cc, ah[mt], bh + h8 * 2);
                        mma16816(cc, ah[mt], bl + h8 * 2);
                        mma16816(cc, al[mt], bh + h8 * 2);
                    }
                }
            }
        }
    }

    float qs = (mode == 1 && z == 0) ? 0.125f : 1.0f;
#pragma unroll
    for (int mt = 0; mt < 2; mt++) {
#pragma unroll
        for (int nt8 = 0; nt8 < 8; nt8++) {
            const float* cc = acc[mt][nt8];
            int row = m0 + wm * 32 + mt * 16 + (lane >> 2);
            int col = n0 + wn * 64 + nt8 * 8 + (lane & 3) * 2;
            float bx2 = bias[col], by2 = bias[col + 1];
            float2 v0 = make_float2((cc[0] + bx2) * qs, (cc[1] + by2) * qs);
            float2 v1 = make_float2((cc[2] + bx2) * qs, (cc[3] + by2) * qs);
            if (mode == 1) {
                uint32_t* Ph = (z == 0) ? g_qh : (z == 1) ? g_kh : g_vh;
                uint32_t* Pl = (z == 0) ? g_ql : (z == 1) ? g_kl : g_vl;
                int h = col >> 6, d = col & 63;
                int bb = row >> 9, s = row & 511;
                size_t p0 = (((size_t)((bb * 16 + h) * 512 + s)) * 64 + d) >> 1;
                int bb2 = (row + 8) >> 9, s2 = (row + 8) & 511;
                size_t p1 = (((size_t)((bb2 * 16 + h) * 512 + s2)) * 64 + d) >> 1;
                uint32_t hi, lo;
                split2(v0.x, v0.y, hi, lo);
                Ph[p0] = hi; Pl[p0] = lo;
                split2(v1.x, v1.y, hi, lo);
                Ph[p1] = hi; Pl[p1] = lo;
            } else {
                *(float2*)&C0[(size_t)row * 1024 + col] = v0;
                *(float2*)&C0[(size_t)(row + 8) * 1024 + col] = v1;
            }
        }
    }
}

// ---- bias block body (fp16x2 HMMA + coalesced smem-transposed stores) --------
__device__ __forceinline__ void bias_block_body(
        int blk, char* bsm, const float* Wg, const float* bg) {
    __shared__ float bgs[16];
    uint32_t sb = smem_u32(bsm);
    int tid = threadIdx.x, lane = tid & 31, w = tid >> 5;
    int m0 = (blk & 1) * 256;
    int n  = (blk >> 1) & 511;
    int b  = blk >> 10;
    int m  = m0 + tid;

    if (tid < 16) bgs[tid] = bg[tid];
    {
        int row = tid >> 4, k4 = (tid & 15) * 4;
        float4 wv4 = *(const float4*)(Wg + row * 64 + k4);
        uint32_t h0, l0, h1, l1;
        split2h(wv4.x, wv4.y, h0, l0);
        split2h(wv4.z, wv4.w, h1, l1);
        *(uint2*)(bsm + 73728 + row * 144 + k4 * 2) = make_uint2(h0, h1);
        *(uint2*)(bsm + 76032 + row * 144 + k4 * 2) = make_uint2(l0, l1);
    }

    const float* fn = g_boxf + (size_t)(b * 512 + n) * 8;
    const float* fm = g_boxf + (size_t)(b * 512 + m) * 8;
    float pos[4];
    pos[0] = __logf(fmaxf(fabsf(fn[0] - fm[0]) / fn[2], 1e-3f)) * 100.0f;
    pos[1] = __logf(fmaxf(fabsf(fn[1] - fm[1]) / fn[3], 1e-3f)) * 100.0f;
    pos[2] = (fn[4] - fm[4]) * 100.0f;
    pos[3] = (fn[5] - fm[5]) * 100.0f;

    const float DMAT[8] = {1.0f, 0.4216965034f, 0.1778279410f, 0.0749894209f,
                           0.0316227766f, 0.0133352143f, 0.0056234133f, 0.0023713737f};

#pragma unroll
    for (int d = 0; d < 4; d++) {
        float sv[8], cv[8];
#pragma unroll
        for (int j = 0; j < 8; j++) __sincosf(pos[d] * DMAT[j], &sv[j], &cv[j]);
        uint32_t sh[4], sl[4], ch[4], cl[4];
#pragma unroll
        for (int p = 0; p < 4; p++) {
            split2h(sv[2*p], sv[2*p+1], sh[p], sl[p]);
            split2h(cv[2*p], cv[2*p+1], ch[p], cl[p]);
        }
        *(uint4*)(bsm + tid * 144 + d * 16)          = make_uint4(sh[0], sh[1], sh[2], sh[3]);
        *(uint4*)(bsm + 36864 + tid * 144 + d * 16)  = make_uint4(sl[0], sl[1], sl[2], sl[3]);
        *(uint4*)(bsm + tid * 144 + (4 + d) * 16)         = make_uint4(ch[0], ch[1], ch[2], ch[3]);
        *(uint4*)(bsm + 36864 + tid * 144 + (4 + d) * 16) = make_uint4(cl[0], cl[1], cl[2], cl[3]);
    }
    __syncthreads();

    uint32_t aOff = sb + (uint32_t)(w * 32 + (lane & 15)) * 144 + (uint32_t)(lane >> 4) * 16;
    uint32_t bOff = sb + 73728 + (uint32_t)((lane & 7) + ((lane >> 4) & 1) * 8) * 144
                  + (uint32_t)((lane >> 3) & 1) * 16;
    float acc[2][2][4];
#pragma unroll
    for (int mt = 0; mt < 2; mt++)
#pragma unroll
        for (int n8 = 0; n8 < 2; n8++)
#pragma unroll
            for (int qq = 0; qq < 4; qq++) acc[mt][n8][qq] = 0.0f;

#pragma unroll
    for (int k16 = 0; k16 < 4; k16++) {
        uint32_t bh4[4], bl4[4];
        LDSM4(bh4, bOff + k16 * 32);
        LDSM4(bl4, bOff + 2304 + k16 * 32);
#pragma unroll
        for (int mt = 0; mt < 2; mt++) {
            uint32_t ah[4], al[4];
            LDSM4(ah, aOff + (uint32_t)mt * (16 * 144) + k16 * 32);
            LDSM4(al, aOff + 36864 + (uint32_t)mt * (16 * 144) + k16 * 32);
#pragma unroll
            for (int n8 = 0; n8 < 2; n8++) {
                float* cc = acc[mt][n8];
                mma16816h(cc, ah, bh4 + n8 * 2);
                mma16816h(cc, ah, bl4 + n8 * 2);
                mma16816h(cc, al, bh4 + n8 * 2);
            }
        }
    }

    // transpose through smem (pitch 260 floats -> conflict-free), then
    // coalesced 1KB-per-head global stores
    __syncthreads();
    float* tr = (float*)bsm;     // 16 heads x 260-float pitch = 16640 B
#pragma unroll
    for (int mt = 0; mt < 2; mt++) {
#pragma unroll
        for (int n8 = 0; n8 < 2; n8++) {
#pragma unroll
            for (int r2 = 0; r2 < 2; r2++) {
#pragma unroll
                for (int j = 0; j < 2; j++) {
                    int row = w * 32 + mt * 16 + (lane >> 2) + r2 * 8;
                    int col = n8 * 8 + (lane & 3) * 2 + j;
                    float g = acc[mt][n8][r2 * 2 + j] + bgs[col];
                    tr[col * 260 + row] = __logf(fmaxf(g, 1e-6f));
                }
            }
        }
    }
    __syncthreads();
    {
        int h = tid >> 4, mseg = (tid & 15) * 16;
        size_t gb = ((size_t)(b * 16 + h)) * 262144 + (size_t)n * 512 + m0 + mseg;
        const float* src = tr + h * 260 + mseg;
#pragma unroll
        for (int q = 0; q < 4; q++)
            *(float4*)&g_logb[gb + q * 4] = *(const float4*)(src + q * 4);
    }
}

// ---- fused launch. has_bias: interleaved 3 GEMM + 32 bias per 35-block group.
__global__ __launch_bounds__(256, 2) void fused_gemm_bias_kernel(
        const float* __restrict__ b0p, const float* __restrict__ b1p,
        const float* __restrict__ b2p, float* __restrict__ C0,
        const float* __restrict__ Wg, const float* __restrict__ bg,
        int a_sel, int mode, int has_bias) {
    extern __shared__ char smem[];
    int id = blockIdx.x;
    if (!has_bias) {
        int z = id >> 8, rem = id & 255;
        gemm_tile_body(rem & 31, rem >> 5, z, smem, b0p, b1p, b2p, C0, a_sel, mode);
        return;
    }
    int grp = id / 35, rem = id - grp * 35;
    if (rem < 3) {
        int g = grp * 3 + rem;          // 0..767
        int z = g >> 8, r2 = g & 255;
        gemm_tile_body(r2 & 31, r2 >> 5, z, smem, b0p, b1p, b2p, C0, a_sel, mode);
    } else {
        bias_block_body(grp * 32 + (rem - 3), smem, Wg, bg);
    }
}

// ============ tensor-core flash attention, q-tile 128, 256 threads ============
static constexpr uint32_t ABUF = 36864;
static constexpr int ATTN_SMEM = 2 * 36864;   // 73728

__global__ __launch_bounds__(256) void attn_mma_kernel() {
    extern __shared__ __align__(16) char asmem[];
    uint32_t sbase = smem_u32(asmem);
    int tid = threadIdx.x, lane = tid & 31, w = tid >> 5;   // 8 warps
    int q0 = blockIdx.x * 128, bh = blockIdx.y;
    size_t bhb = (size_t)bh * 65536;
    const char* pqh = (const char*)g_qh + bhb + (size_t)q0 * 128;
    const char* pql = (const char*)g_ql + bhb + (size_t)q0 * 128;
    const char* pkh = (const char*)g_kh + bhb;
    const char* pkl = (const char*)g_kl + bhb;
    const char* pvh = (const char*)g_vh + bhb;
    const char* pvl = (const char*)g_vl + bhb;
    const float* lbp = g_logb + (size_t)bh * 262144;

    // stage Q (128 rows) into buf1: hi @ +0, lo @ +18432
#pragma unroll
    for (int p = 0; p < 4; p++) {
        int id = tid + p * 256, row = id >> 3, seg = id & 7;
        uint32_t d = sbase + ABUF + (uint32_t)row * 144 + (uint32_t)seg * 16;
        int so = row * 128 + seg * 16;
        CP_ASYNC16(d, pqh + so);
        CP_ASYNC16(d + 18432, pql + so);
    }
    CP_COMMIT();
    // chunk 0 (64 keys) into buf0
#pragma unroll
    for (int p = 0; p < 2; p++) {
        int id = tid + p * 256, row = id >> 3, seg = id & 7;
        uint32_t d = sbase + (uint32_t)row * 144 + (uint32_t)seg * 16;
        int so = row * 128 + seg * 16;
        CP_ASYNC16(d,         pkh + so);
        CP_ASYNC16(d + 9216,  pkl + so);
        CP_ASYNC16(d + 18432, pvh + so);
        CP_ASYNC16(d + 27648, pvl + so);
    }
    CP_COMMIT();
    CP_WAIT(1);
    __syncthreads();

    uint32_t qh[4][4], ql[4][4];
    {
        uint32_t aOff = (uint32_t)(w * 16 + (lane & 15)) * 144 + (uint32_t)(lane >> 4) * 16;
#pragma unroll
        for (int k16 = 0; k16 < 4; k16++) {
            LDSM4(qh[k16], sbase + ABUF + aOff + k16 * 32);
            LDSM4(ql[k16], sbase + ABUF + 18432 + aOff + k16 * 32);
        }
    }
    __syncthreads();          // Q region free for K/V chunk 1

    float o[8][4];
#pragma unroll
    for (int t = 0; t < 8; t++)
#pragma unroll
        for (int q = 0; q < 4; q++) o[t][q] = 0.0f;
    float m0 = -1e30f, m1 = -1e30f, l0 = 0.0f, l1 = 0.0f;

    uint32_t bOffK = (uint32_t)((lane & 7) + ((lane >> 4) & 1) * 8) * 144
                   + (uint32_t)((lane >> 3) & 1) * 16;
    uint32_t vOff  = (uint32_t)((lane & 7) + ((lane >> 3) & 1) * 8) * 144
                   + (uint32_t)(lane >> 4) * 16;

    for (int c = 0; c < 8; c++) {
        if (c < 7) {
            int k0 = (c + 1) * 64;
            uint32_t bb = sbase + (uint32_t)((c + 1) & 1) * ABUF;
#pragma unroll
            for (int p = 0; p < 2; p++) {
                int id = tid + p * 256, row = id >> 3, seg = id & 7;
                uint32_t d = bb + (uint32_t)row * 144 + (uint32_t)seg * 16;
                int so = (k0 + row) * 128 + seg * 16;
                CP_ASYNC16(d,         pkh + so);
                CP_ASYNC16(d + 9216,  pkl + so);
                CP_ASYNC16(d + 18432, pvh + so);
                CP_ASYNC16(d + 27648, pvl + so);
            }
            CP_COMMIT();
            CP_WAIT(1);
        } else {
            CP_WAIT(0);
        }
        __syncthreads();
        uint32_t sb = sbase + (uint32_t)(c & 1) * ABUF;

        const float* lp = lbp + (size_t)(q0 + w * 16 + (lane >> 2)) * 512
                        + c * 64 + (lane & 3) * 2;
        float2 lbA[8], lbB[8];
#pragma unroll
        for (int t = 0; t < 8; t++) {
            lbA[t] = *(const float2*)(lp + t * 8);
            lbB[t] = *(const float2*)(lp + 4096 + t * 8);
        }

        float s[8][4];
#pragma unroll
        for (int t = 0; t < 8; t++)
#pragma unroll
            for (int q = 0; q < 4; q++) s[t][q] = 0.0f;
#pragma unroll
        for (int k16 = 0; k16 < 4; k16++) {
#pragma unroll
            for (int ntp = 0; ntp < 4; ntp++) {
                uint32_t bh4[4], bl4[4];
                uint32_t bo = sb + bOffK + (uint32_t)ntp * 2304 + (uint32_t)k16 * 32;
                LDSM4(bh4, bo);
                LDSM4(bl4, bo + 9216);
#pragma unroll
                for (int h8 = 0; h8 < 2; h8++) {
                    float* cc = s[ntp * 2 + h8];
                    mma16816(cc, qh[k16], bh4 + h8 * 2);
                    mma16816(cc, ql[k16], bh4 + h8 * 2);
                    mma16816(cc, qh[k16], bl4 + h8 * 2);
                }
            }
        }

        float rm0 = -1e30f, rm1 = -1e30f;
#pragma unroll
        for (int t = 0; t < 8; t++) {
            s[t][0] += lbA[t].x; s[t][1] += lbA[t].y;
            s[t][2] += lbB[t].x; s[t][3] += lbB[t].y;
            rm0 = fmaxf(rm0, fmaxf(s[t][0], s[t][1]));
            rm1 = fmaxf(rm1, fmaxf(s[t][2], s[t][3]));
        }
        rm0 = fmaxf(rm0, __shfl_xor_sync(0xffffffffu, rm0, 1, 4));
        rm0 = fmaxf(rm0, __shfl_xor_sync(0xffffffffu, rm0, 2, 4));
        rm1 = fmaxf(rm1, __shfl_xor_sync(0xffffffffu, rm1, 1, 4));
        rm1 = fmaxf(rm1, __shfl_xor_sync(0xffffffffu, rm1, 2, 4));
        float mn0 = fmaxf(m0, rm0), mn1 = fmaxf(m1, rm1);
        float c0 = __expf(m0 - mn0), c1 = __expf(m1 - mn1);
        m0 = mn0; m1 = mn1;
        float ps0 = 0.0f, ps1 = 0.0f;
#pragma unroll
        for (int t = 0; t < 8; t++) {
            s[t][0] = __expf(s[t][0] - mn0); ps0 += s[t][0];
            s[t][1] = __expf(s[t][1] - mn0); ps0 += s[t][1];
            s[t][2] = __expf(s[t][2] - mn1); ps1 += s[t][2];
            s[t][3] = __expf(s[t][3] - mn1); ps1 += s[t][3];
        }
        ps0 += __shfl_xor_sync(0xffffffffu, ps0, 1, 4);
        ps0 += __shfl_xor_sync(0xffffffffu, ps0, 2, 4);
        ps1 += __shfl_xor_sync(0xffffffffu, ps1, 1, 4);
        ps1 += __shfl_xor_sync(0xffffffffu, ps1, 2, 4);
        l0 = l0 * c0 + ps0; l1 = l1 * c1 + ps1;
#pragma unroll
        for (int t = 0; t < 8; t++) {
            o[t][0] *= c0; o[t][1] *= c0; o[t][2] *= c1; o[t][3] *= c1;
        }

        uint32_t ph[4][4], pl[4][4];
#pragma unroll
        for (int j = 0; j < 4; j++) {
            split2(s[2*j][0],   s[2*j][1],   ph[j][0], pl[j][0]);
            split2(s[2*j][2],   s[2*j][3],   ph[j][1], pl[j][1]);
            split2(s[2*j+1][0], s[2*j+1][1], ph[j][2], pl[j][2]);
            split2(s[2*j+1][2], s[2*j+1][3], ph[j][3], pl[j][3]);
        }

#pragma unroll
        for (int j = 0; j < 4; j++) {
#pragma unroll
            for (int np = 0; np < 4; np++) {
                uint32_t vh4[4], vl4[4];
                uint32_t vo = sb + 18432 + vOff + (uint32_t)j * 2304 + (uint32_t)np * 32;
                LDSM4T(vh4, vo);
                LDSM4T(vl4, vo + 9216);
#pragma unroll
                for (int h8 = 0; h8 < 2; h8++) {
                    float* cc = o[np * 2 + h8];
                    mma16816(cc, ph[j], vh4 + h8 * 2);
                    mma16816(cc, pl[j], vh4 + h8 * 2);
                    mma16816(cc, ph[j], vl4 + h8 * 2);
                }
            }
        }
        __syncthreads();
    }

    float i0 = 1.0f / l0, i1 = 1.0f / l1;
    int b = bh >> 4, hh = bh & 15;
    int r0 = q0 + w * 16 + (lane >> 2);
    size_t base0 = ((size_t)(b * 512 + r0) * 1024 + hh * 64 + (lane & 3) * 2) >> 1;
    size_t base1 = ((size_t)(b * 512 + r0 + 8) * 1024 + hh * 64 + (lane & 3) * 2) >> 1;
#pragma unroll
    for (int t = 0; t < 8; t++) {
        uint32_t hi, lo;
        split2(o[t][0] * i0, o[t][1] * i0, hi, lo);
        g_oh[base0 + t * 4] = hi; g_ol[base0 + t * 4] = lo;
        split2(o[t][2] * i1, o[t][3] * i1, hi, lo);
        g_oh[base1 + t * 4] = hi; g_ol[base1 + t * 4] = lo;
    }
}

// ---------------- launch ------------------------------------------------------
extern "C" void kernel_launch(void* const* d_in, const int* in_sizes, int n_in,
                              void* d_out, int out_size) {
    (void)in_sizes; (void)n_in; (void)out_size;
    const float* queries = (const float*)d_in[0];
    const float* keys    = (const float*)d_in[1];
    const float* values  = (const float*)d_in[2];
    const float* boxes   = (const float*)d_in[3];
    const float* bq = (const float*)d_in[5];
    const float* bk = (const float*)d_in[7];
    const float* bv = (const float*)d_in[9];
    const float* bo = (const float*)d_in[11];
    const float* Wq = (const float*)d_in[4];
    const float* Wk = (const float*)d_in[6];
    const float* Wv = (const float*)d_in[8];
    const float* Wo = (const float*)d_in[10];
    const float* Wg = (const float*)d_in[12];
    const float* bg = (const float*)d_in[13];
    float* out = (float*)d_out;

    cudaFuncSetAttribute(fused_gemm_bias_kernel,
                         cudaFuncAttributeMaxDynamicSharedMemorySize, FUSED_SMEM);
    cudaFuncSetAttribute(attn_mma_kernel,
                         cudaFuncAttributeMaxDynamicSharedMemorySize, ATTN_SMEM);

    boxfeat_kernel<<<16, 256>>>(boxes);
    conv_all_kernel<<<16384, 256>>>(queries, keys, values, Wq, Wk, Wv, Wo);
    // QKV projections + geometry bias, interleaved 3:32 per 35-block group
    fused_gemm_bias_kernel<<<8960, 256, FUSED_SMEM>>>(
        bq, bk, bv, nullptr, Wg, bg, /*a_sel=*/0, /*mode=*/1, /*has_bias=*/1);
    attn_mma_kernel<<<dim3(4, 128), 256, ATTN_SMEM>>>();
    // output projection (GEMM-only blocks)
    fused_gemm_bias_kernel<<<256, 256, FUSED_SMEM>>>(
        bo, bo, bo, out, Wg, bg, /*a_sel=*/1, /*mode=*/0, /*has_bias=*/0);
}

// round 15
// speedup vs baseline: 1.2087x; 1.2087x over previous
#include <cuda_runtime.h>
#include <cuda_bf16.h>
#include <cuda_fp16.h>
#include <cstdint>

#define Bsz 8
#define Nsq 512
#define DM_ 1024
#define Hh 16
#define DK 64

// ---------------- scratch (static device arrays; no allocation) --------------
__device__ float g_logb[(size_t)Bsz*Hh*Nsq*Nsq]; // (b,h,n,m) fp32
__device__ float g_boxf[Bsz*Nsq*8];               // cx,cy,w,h,logw,logh
__device__ uint32_t g_qh[Bsz*Hh*Nsq*DK/2];
__device__ uint32_t g_ql[Bsz*Hh*Nsq*DK/2];
__device__ uint32_t g_kh[Bsz*Hh*Nsq*DK/2];
__device__ uint32_t g_kl[Bsz*Hh*Nsq*DK/2];
__device__ uint32_t g_vh[Bsz*Hh*Nsq*DK/2];
__device__ uint32_t g_vl[Bsz*Hh*Nsq*DK/2];
__device__ uint32_t g_inh[3u*4096*512];
__device__ uint32_t g_inl[3u*4096*512];
__device__ uint32_t g_wh[4u*1024*512];
__device__ uint32_t g_wl[4u*1024*512];
__device__ uint32_t g_oh[4096u*512];
__device__ uint32_t g_ol[4096u*512];

// ---------------- helpers ----------------------------------------------------
__device__ __forceinline__ uint32_t smem_u32(const void* p) {
    uint32_t a;
    asm("{ .reg .u64 t; cvta.to.shared.u64 t, %1; cvt.u32.u64 %0, t; }" : "=r"(a) : "l"(p));
    return a;
}

#define LDSM4(r, a) \
    asm volatile("ldmatrix.sync.aligned.m8n8.x4.shared.b16 {%0,%1,%2,%3}, [%4];" \
        : "=r"((r)[0]), "=r"((r)[1]), "=r"((r)[2]), "=r"((r)[3]) : "r"(a))
#define LDSM4T(r, a) \
    asm volatile("ldmatrix.sync.aligned.m8n8.x4.trans.shared.b16 {%0,%1,%2,%3}, [%4];" \
        : "=r"((r)[0]), "=r"((r)[1]), "=r"((r)[2]), "=r"((r)[3]) : "r"(a))

#define CP_ASYNC16(dst, src) \
    asm volatile("cp.async.cg.shared.global [%0], [%1], 16;" :: "r"(dst), "l"(src) : "memory")
#define CP_COMMIT() asm volatile("cp.async.commit_group;" ::: "memory")
#define CP_WAIT(n)  asm volatile("cp.async.wait_group %0;" :: "n"(n) : "memory")

__device__ __forceinline__ void mma16816(float* c, const uint32_t* a, const uint32_t* b) {
    asm volatile("mma.sync.aligned.m16n8k16.row.col.f32.bf16.bf16.f32 "
        "{%0,%1,%2,%3}, {%4,%5,%6,%7}, {%8,%9}, {%0,%1,%2,%3};"
        : "+f"(c[0]), "+f"(c[1]), "+f"(c[2]), "+f"(c[3])
        : "r"(a[0]), "r"(a[1]), "r"(a[2]), "r"(a[3]), "r"(b[0]), "r"(b[1]));
}
__device__ __forceinline__ void mma16816h(float* c, const uint32_t* a, const uint32_t* b) {
    asm volatile("mma.sync.aligned.m16n8k16.row.col.f32.f16.f16.f32 "
        "{%0,%1,%2,%3}, {%4,%5,%6,%7}, {%8,%9}, {%0,%1,%2,%3};"
        : "+f"(c[0]), "+f"(c[1]), "+f"(c[2]), "+f"(c[3])
        : "r"(a[0]), "r"(a[1]), "r"(a[2]), "r"(a[3]), "r"(b[0]), "r"(b[1]));
}

__device__ __forceinline__ void split2(float x, float y, uint32_t& hi, uint32_t& lo) {
    asm("cvt.rn.bf16x2.f32 %0, %1, %2;" : "=r"(hi) : "f"(y), "f"(x));
    float fx = __uint_as_float(hi << 16);
    float fy = __uint_as_float(hi & 0xffff0000u);
    asm("cvt.rn.bf16x2.f32 %0, %1, %2;" : "=r"(lo) : "f"(y - fy), "f"(x - fx));
}
__device__ __forceinline__ void split2h(float x, float y, uint32_t& hi, uint32_t& lo) {
    __half2 h = __floats2half2_rn(x, y);
    hi = *reinterpret_cast<uint32_t*>(&h);
    float2 f = __half22float2(h);
    __half2 l = __floats2half2_rn(x - f.x, y - f.y);
    lo = *reinterpret_cast<uint32_t*>(&l);
}

// ---------------- box feature precompute ------------------------------------
__global__ void boxfeat_kernel(const float* __restrict__ boxes) {
    int i = blockIdx.x * 256 + threadIdx.x;
    float4 bx = *(const float4*)(boxes + (size_t)i * 4);
    float cx = (bx.x + bx.z) * 0.5f;
    float cy = (bx.y + bx.w) * 0.5f;
    float w  = (bx.z - bx.x) + 1.0f;
    float h  = (bx.w - bx.y) + 1.0f;
    float* o = g_boxf + (size_t)i * 8;
    o[0] = cx; o[1] = cy; o[2] = w; o[3] = h;
    o[4] = __logf(w); o[5] = __logf(h);
}

// ---------------- fused f32 -> bf16 hi/lo conversion (all 7 tensors) ----------
__global__ void conv_all_kernel(const float* __restrict__ q, const float* __restrict__ k,
                                const float* __restrict__ v, const float* __restrict__ wq,
                                const float* __restrict__ wk, const float* __restrict__ wv,
                                const float* __restrict__ wo) {
    size_t i = (size_t)blockIdx.x * 256 + threadIdx.x;
    const float* src;
    uint32_t *dh, *dl;
    size_t off;
    if (i < 3145728) {
        int sel = (int)(i >> 20);
        off = i & 1048575;
        src = (sel == 0) ? q : (sel == 1) ? k : v;
        dh = g_inh + (size_t)sel * 2097152;
        dl = g_inl + (size_t)sel * 2097152;
    } else {
        size_t j = i - 3145728;
        int sel = (int)(j >> 18);
        off = j & 262143;
        src = (sel == 0) ? wq : (sel == 1) ? wk : (sel == 2) ? wv : wo;
        dh = g_wh + (size_t)sel * 524288;
        dl = g_wl + (size_t)sel * 524288;
    }
    float4 x = *(const float4*)(src + off * 4);
    uint32_t h0, l0, h1, l1;
    split2(x.x, x.y, h0, l0);
    split2(x.z, x.w, h1, l1);
    *(uint2*)(dh + off * 2) = make_uint2(h0, h1);
    *(uint2*)(dl + off * 2) = make_uint2(l0, l1);
}

// ============ device bodies: GEMM tile and bias block =========================
static constexpr int STAGE_B = 4 * 128 * 64;          // 32768
static constexpr int FUSED_SMEM = 3 * STAGE_B;        // 98304

__device__ __forceinline__ void gemm_tile_body(
        int bx, int by, int bz, char* smem,
        const float* b0p, const float* b1p, const float* b2p,
        float* C0, int a_sel, int mode) {
    int z = bz;
    const uint32_t* Ah;
    const uint32_t* Al;
    if (a_sel) { Ah = g_oh; Al = g_ol; }
    else       { Ah = g_inh + (size_t)z * 2097152; Al = g_inl + (size_t)z * 2097152; }
    int wsel = a_sel ? 3 : z;
    const uint32_t* Wh = g_wh + (size_t)wsel * 524288;
    const uint32_t* Wl = g_wl + (size_t)wsel * 524288;
    const float* bias = (z == 0) ? b0p : (z == 1) ? b1p : b2p;

    uint32_t sbase = smem_u32(smem);
    int tid = threadIdx.x;
    int lane = tid & 31, wid = tid >> 5;
    int wm = wid & 3, wn = wid >> 2;
    int m0 = bx * 128, n0 = by * 128;

    const uint32_t* srcb[4];
    srcb[0] = Ah + (size_t)m0 * 512;
    srcb[1] = Al + (size_t)m0 * 512;
    srcb[2] = Wh + (size_t)n0 * 512;
    srcb[3] = Wl + (size_t)n0 * 512;

    int arow0 = wm * 32 + (lane & 15);
    uint32_t ahalf = (uint32_t)(lane >> 4);
    int brow0 = wn * 64 + (lane & 7) + ((lane >> 4) & 1) * 8;
    uint32_t bhalf = (uint32_t)((lane >> 3) & 1);

    float acc[2][8][4];
#pragma unroll
    for (int i = 0; i < 2; i++)
#pragma unroll
        for (int j = 0; j < 8; j++)
#pragma unroll
            for (int q = 0; q < 4; q++) acc[i][j][q] = 0.0f;

#pragma unroll
    for (int pc = 0; pc < 2; pc++) {
        uint32_t bb = sbase + (uint32_t)pc * STAGE_B;
        int k0 = pc * 16;
#pragma unroll
        for (int p = 0; p < 8; p++) {
            int mat = p >> 1;
            int id2 = tid + (p & 1) * 256;
            int row = id2 >> 2, seg = id2 & 3;
            uint32_t dst = bb + (uint32_t)mat * 8192 + (uint32_t)row * 64
                         + (uint32_t)((seg ^ ((row >> 1) & 3)) * 16);
            CP_ASYNC16(dst, srcb[mat] + (size_t)row * 512 + k0 + seg * 4);
        }
        CP_COMMIT();
    }

    for (int c = 0; c < 32; ++c) {
        if (c < 31) { CP_WAIT(1); } else { CP_WAIT(0); }
        __syncthreads();

        if (c + 2 < 32) {
            uint32_t bb = sbase + (uint32_t)((c + 2) % 3) * STAGE_B;
            int k0 = (c + 2) * 16;
#pragma unroll
            for (int p = 0; p < 8; p++) {
                int mat = p >> 1;
                int id2 = tid + (p & 1) * 256;
                int row = id2 >> 2, seg = id2 & 3;
                uint32_t dst = bb + (uint32_t)mat * 8192 + (uint32_t)row * 64
                             + (uint32_t)((seg ^ ((row >> 1) & 3)) * 16);
                CP_ASYNC16(dst, srcb[mat] + (size_t)row * 512 + k0 + seg * 4);
            }
            CP_COMMIT();
        }

        uint32_t base = sbase + (uint32_t)(c % 3) * STAGE_B;
#pragma unroll
        for (int k16 = 0; k16 < 2; k16++) {
            uint32_t ah[2][4], al[2][4];
#pragma unroll
            for (int mt = 0; mt < 2; mt++) {
                int ar = arow0 + mt * 16;
                uint32_t aseg = ((uint32_t)(k16 * 2) + ahalf) ^ ((uint32_t)(ar >> 1) & 3u);
                uint32_t ao = base + (uint32_t)ar * 64 + aseg * 16;
                LDSM4(ah[mt], ao);
                LDSM4(al[mt], ao + 8192);
            }
#pragma unroll
            for (int ntp = 0; ntp < 4; ntp++) {
                uint32_t bh[4], bl[4];
                int br = brow0 + ntp * 16;
                uint32_t bseg = ((uint32_t)(k16 * 2) + bhalf) ^ ((uint32_t)(br >> 1) & 3u);
                uint32_t bo = base + 16384 + (uint32_t)br * 64 + bseg * 16;
                LDSM4(bh, bo);
                LDSM4(bl, bo + 8192);
#pragma unroll
                for (int mt = 0; mt < 2; mt++) {
#pragma unroll
                    for (int h8 = 0; h8 < 2; h8++) {
                        float* cc = acc[mt][ntp * 2 + h8];
                        mma16816(cc, ah[mt], bh + h8 * 2);
                        mma16816(cc, ah[mt], bl + h8 * 2);
                        mma16816(cc, al[mt], bh + h8 * 2);
                    }
                }
            }
        }
    }

    float qs = (mode == 1 && z == 0) ? 0.125f : 1.0f;
#pragma unroll
    for (int mt = 0; mt < 2; mt++) {
#pragma unroll
        for (int nt8 = 0; nt8 < 8; nt8++) {
            const float* cc = acc[mt][nt8];
            int row = m0 + wm * 32 + mt * 16 + (lane >> 2);
            int col = n0 + wn * 64 + nt8 * 8 + (lane & 3) * 2;
            float bx2 = bias[col], by2 = bias[col + 1];
            float2 v0 = make_float2((cc[0] + bx2) * qs, (cc[1] + by2) * qs);
            float2 v1 = make_float2((cc[2] + bx2) * qs, (cc[3] + by2) * qs);
            if (mode == 1) {
                uint32_t* Ph = (z == 0) ? g_qh : (z == 1) ? g_kh : g_vh;
                uint32_t* Pl = (z == 0) ? g_ql : (z == 1) ? g_kl : g_vl;
                int h = col >> 6, d = col & 63;
                int bb = row >> 9, s = row & 511;
                size_t p0 = (((size_t)((bb * 16 + h) * 512 + s)) * 64 + d) >> 1;
                int bb2 = (row + 8) >> 9, s2 = (row + 8) & 511;
                size_t p1 = (((size_t)((bb2 * 16 + h) * 512 + s2)) * 64 + d) >> 1;
                uint32_t hi, lo;
                split2(v0.x, v0.y, hi, lo);
                Ph[p0] = hi; Pl[p0] = lo;
                split2(v1.x, v1.y, hi, lo);
                Ph[p1] = hi; Pl[p1] = lo;
            } else {
                *(float2*)&C0[(size_t)row * 1024 + col] = v0;
                *(float2*)&C0[(size_t)(row + 8) * 1024 + col] = v1;
            }
        }
    }
}

// ---- bias block body (fp16x2 HMMA + coalesced smem-transposed stores) --------
__device__ __forceinline__ void bias_block_body(
        int blk, char* bsm, const float* Wg, const float* bg) {
    __shared__ float bgs[16];
    uint32_t sb = smem_u32(bsm);
    int tid = threadIdx.x, lane = tid & 31, w = tid >> 5;
    int m0 = (blk & 1) * 256;
    int n  = (blk >> 1) & 511;
    int b  = blk >> 10;
    int m  = m0 + tid;

    if (tid < 16) bgs[tid] = bg[tid];
    {
        int row = tid >> 4, k4 = (tid & 15) * 4;
        float4 wv4 = *(const float4*)(Wg + row * 64 + k4);
        uint32_t h0, l0, h1, l1;
        split2h(wv4.x, wv4.y, h0, l0);
        split2h(wv4.z, wv4.w, h1, l1);
        *(uint2*)(bsm + 73728 + row * 144 + k4 * 2) = make_uint2(h0, h1);
        *(uint2*)(bsm + 76032 + row * 144 + k4 * 2) = make_uint2(l0, l1);
    }

    const float* fn = g_boxf + (size_t)(b * 512 + n) * 8;
    const float* fm = g_boxf + (size_t)(b * 512 + m) * 8;
    float pos[4];
    pos[0] = __logf(fmaxf(fabsf(fn[0] - fm[0]) / fn[2], 1e-3f)) * 100.0f;
    pos[1] = __logf(fmaxf(fabsf(fn[1] - fm[1]) / fn[3], 1e-3f)) * 100.0f;
    pos[2] = (fn[4] - fm[4]) * 100.0f;
    pos[3] = (fn[5] - fm[5]) * 100.0f;

    const float DMAT[8] = {1.0f, 0.4216965034f, 0.1778279410f, 0.0749894209f,
                           0.0316227766f, 0.0133352143f, 0.0056234133f, 0.0023713737f};

#pragma unroll
    for (int d = 0; d < 4; d++) {
        float sv[8], cv[8];
#pragma unroll
        for (int j = 0; j < 8; j++) __sincosf(pos[d] * DMAT[j], &sv[j], &cv[j]);
        uint32_t sh[4], sl[4], ch[4], cl[4];
#pragma unroll
        for (int p = 0; p < 4; p++) {
            split2h(sv[2*p], sv[2*p+1], sh[p], sl[p]);
            split2h(cv[2*p], cv[2*p+1], ch[p], cl[p]);
        }
        *(uint4*)(bsm + tid * 144 + d * 16)          = make_uint4(sh[0], sh[1], sh[2], sh[3]);
        *(uint4*)(bsm + 36864 + tid * 144 + d * 16)  = make_uint4(sl[0], sl[1], sl[2], sl[3]);
        *(uint4*)(bsm + tid * 144 + (4 + d) * 16)         = make_uint4(ch[0], ch[1], ch[2], ch[3]);
        *(uint4*)(bsm + 36864 + tid * 144 + (4 + d) * 16) = make_uint4(cl[0], cl[1], cl[2], cl[3]);
    }
    __syncthreads();

    uint32_t aOff = sb + (uint32_t)(w * 32 + (lane & 15)) * 144 + (uint32_t)(lane >> 4) * 16;
    uint32_t bOff = sb + 73728 + (uint32_t)((lane & 7) + ((lane >> 4) & 1) * 8) * 144
                  + (uint32_t)((lane >> 3) & 1) * 16;
    float acc[2][2][4];
#pragma unroll
    for (int mt = 0; mt < 2; mt++)
#pragma unroll
        for (int n8 = 0; n8 < 2; n8++)
#pragma unroll
            for (int qq = 0; qq < 4; qq++) acc[mt][n8][qq] = 0.0f;

#pragma unroll
    for (int k16 = 0; k16 < 4; k16++) {
        uint32_t bh4[4], bl4[4];
        LDSM4(bh4, bOff + k16 * 32);
        LDSM4(bl4, bOff + 2304 + k16 * 32);
#pragma unroll
        for (int mt = 0; mt < 2; mt++) {
            uint32_t ah[4], al[4];
            LDSM4(ah, aOff + (uint32_t)mt * (16 * 144) + k16 * 32);
            LDSM4(al, aOff + 36864 + (uint32_t)mt * (16 * 144) + k16 * 32);
#pragma unroll
            for (int n8 = 0; n8 < 2; n8++) {
                float* cc = acc[mt][n8];
                mma16816h(cc, ah, bh4 + n8 * 2);
                mma16816h(cc, ah, bl4 + n8 * 2);
                mma16816h(cc, al, bh4 + n8 * 2);
            }
        }
    }

    __syncthreads();
    float* tr = (float*)bsm;
#pragma unroll
    for (int mt = 0; mt < 2; mt++) {
#pragma unroll
        for (int n8 = 0; n8 < 2; n8++) {
#pragma unroll
            for (int r2 = 0; r2 < 2; r2++) {
#pragma unroll
                for (int j = 0; j < 2; j++) {
                    int row = w * 32 + mt * 16 + (lane >> 2) + r2 * 8;
                    int col = n8 * 8 + (lane & 3) * 2 + j;
                    float g = acc[mt][n8][r2 * 2 + j] + bgs[col];
                    tr[col * 260 + row] = __logf(fmaxf(g, 1e-6f));
                }
            }
        }
    }
    __syncthreads();
    {
        int h = tid >> 4, mseg = (tid & 15) * 16;
        size_t gb = ((size_t)(b * 16 + h)) * 262144 + (size_t)n * 512 + m0 + mseg;
        const float* src = tr + h * 260 + mseg;
#pragma unroll
        for (int q = 0; q < 4; q++)
            *(float4*)&g_logb[gb + q * 4] = *(const float4*)(src + q * 4);
    }
}

// ---- fused launch: blocks [0,768) = QKV GEMM tiles, [768,8960) = bias --------
__global__ __launch_bounds__(256, 2) void fused_gemm_bias_kernel(
        const float* __restrict__ b0p, const float* __restrict__ b1p,
        const float* __restrict__ b2p, float* __restrict__ C0,
        const float* __restrict__ Wg, const float* __restrict__ bg,
        int a_sel, int mode) {
    extern __shared__ char smem[];
    int id = blockIdx.x;
    if (id < 768) {
        int z = id >> 8, rem = id & 255;
        gemm_tile_body(rem & 31, rem >> 5, z, smem, b0p, b1p, b2p, C0, a_sel, mode);
    } else {
        bias_block_body(id - 768, smem, Wg, bg);
    }
}

// ============ tensor-core flash attention, q-tile 64, K-chunk 32 ==============
// Buffers 2 x 18432 B: Kh@0 Kl@4608 Vh@9216 Vl@13824 (32 rows x 144B each).
// Q staged in buf1: hi@18432, lo@27648 (64 rows x 144B each).
static constexpr uint32_t ABUF = 18432;
static constexpr int ATTN_SMEM = 2 * 18432;   // 36864

__global__ __launch_bounds__(128, 4) void attn_mma_kernel() {
    extern __shared__ __align__(16) char asmem[];
    uint32_t sbase = smem_u32(asmem);
    int tid = threadIdx.x, lane = tid & 31, w = tid >> 5;
    int q0 = blockIdx.x * 64, bh = blockIdx.y;
    size_t bhb = (size_t)bh * 65536;
    const char* pqh = (const char*)g_qh + bhb + (size_t)q0 * 128;
    const char* pql = (const char*)g_ql + bhb + (size_t)q0 * 128;
    const char* pkh = (const char*)g_kh + bhb;
    const char* pkl = (const char*)g_kl + bhb;
    const char* pvh = (const char*)g_vh + bhb;
    const char* pvl = (const char*)g_vl + bhb;
    const float* lbp = g_logb + (size_t)bh * 262144;

    // stage Q (64 rows) into buf1 region: hi @ +18432, lo @ +27648
#pragma unroll
    for (int p = 0; p < 4; p++) {
        int id = tid + p * 128, row = id >> 3, seg = id & 7;
        uint32_t d = sbase + ABUF + (uint32_t)row * 144 + (uint32_t)seg * 16;
        int so = row * 128 + seg * 16;
        CP_ASYNC16(d, pqh + so);
        CP_ASYNC16(d + 9216, pql + so);
    }
    CP_COMMIT();
    // chunk 0 (32 keys) into buf0
#pragma unroll
    for (int p = 0; p < 2; p++) {
        int id = tid + p * 128, row = id >> 3, seg = id & 7;
        uint32_t d = sbase + (uint32_t)row * 144 + (uint32_t)seg * 16;
        int so = row * 128 + seg * 16;
        CP_ASYNC16(d,         pkh + so);
        CP_ASYNC16(d + 4608,  pkl + so);
        CP_ASYNC16(d + 9216,  pvh + so);
        CP_ASYNC16(d + 13824, pvl + so);
    }
    CP_COMMIT();
    CP_WAIT(1);
    __syncthreads();

    uint32_t qh[4][4], ql[4][4];
    {
        uint32_t aOff = (uint32_t)(w * 16 + (lane & 15)) * 144 + (uint32_t)(lane >> 4) * 16;
#pragma unroll
        for (int k16 = 0; k16 < 4; k16++) {
            LDSM4(qh[k16], sbase + ABUF + aOff + k16 * 32);
            LDSM4(ql[k16], sbase + ABUF + 9216 + aOff + k16 * 32);
        }
    }
    __syncthreads();          // buf1 free for chunk 1

    float o[8][4];
#pragma unroll
    for (int t = 0; t < 8; t++)
#pragma unroll
        for (int q = 0; q < 4; q++) o[t][q] = 0.0f;
    float m0 = -1e30f, m1 = -1e30f, l0 = 0.0f, l1 = 0.0f;

    uint32_t bOffK = (uint32_t)((lane & 7) + ((lane >> 4) & 1) * 8) * 144
                   + (uint32_t)((lane >> 3) & 1) * 16;
    uint32_t vOff  = (uint32_t)((lane & 7) + ((lane >> 3) & 1) * 8) * 144
                   + (uint32_t)(lane >> 4) * 16;

    for (int c = 0; c < 16; c++) {
        if (c < 15) {
            int k0 = (c + 1) * 32;
            uint32_t bb = sbase + (uint32_t)((c + 1) & 1) * ABUF;
#pragma unroll
            for (int p = 0; p < 2; p++) {
                int id = tid + p * 128, row = id >> 3, seg = id & 7;
                uint32_t d = bb + (uint32_t)row * 144 + (uint32_t)seg * 16;
                int so = (k0 + row) * 128 + seg * 16;
                CP_ASYNC16(d,         pkh + so);
                CP_ASYNC16(d + 4608,  pkl + so);
                CP_ASYNC16(d + 9216,  pvh + so);
                CP_ASYNC16(d + 13824, pvl + so);
            }
            CP_COMMIT();
            CP_WAIT(1);
        } else {
            CP_WAIT(0);
        }
        __syncthreads();
        uint32_t sb = sbase + (uint32_t)(c & 1) * ABUF;

        // logb tile (32 cols)
        const float* lp = lbp + (size_t)(q0 + w * 16 + (lane >> 2)) * 512
                        + c * 32 + (lane & 3) * 2;
        float2 lbA[4], lbB[4];
#pragma unroll
        for (int t = 0; t < 4; t++) {
            lbA[t] = *(const float2*)(lp + t * 8);
            lbB[t] = *(const float2*)(lp + 4096 + t * 8);
        }

        // S = Q K^T  (32 keys)
        float s[4][4];
#pragma unroll
        for (int t = 0; t < 4; t++)
#pragma unroll
            for (int q = 0; q < 4; q++) s[t][q] = 0.0f;
#pragma unroll
        for (int k16 = 0; k16 < 4; k16++) {
#pragma unroll
            for (int ntp = 0; ntp < 2; ntp++) {
                uint32_t bh4[4], bl4[4];
                uint32_t bo = sb + bOffK + (uint32_t)ntp * 2304 + (uint32_t)k16 * 32;
                LDSM4(bh4, bo);
                LDSM4(bl4, bo + 4608);
#pragma unroll
                for (int h8 = 0; h8 < 2; h8++) {
                    float* cc = s[ntp * 2 + h8];
                    mma16816(cc, qh[k16], bh4 + h8 * 2);
                    mma16816(cc, ql[k16], bh4 + h8 * 2);
                    mma16816(cc, qh[k16], bl4 + h8 * 2);
                }
            }
        }

        // bias + online softmax
        float rm0 = -1e30f, rm1 = -1e30f;
#pragma unroll
        for (int t = 0; t < 4; t++) {
            s[t][0] += lbA[t].x; s[t][1] += lbA[t].y;
            s[t][2] += lbB[t].x; s[t][3] += lbB[t].y;
            rm0 = fmaxf(rm0, fmaxf(s[t][0], s[t][1]));
            rm1 = fmaxf(rm1, fmaxf(s[t][2], s[t][3]));
        }
        rm0 = fmaxf(rm0, __shfl_xor_sync(0xffffffffu, rm0, 1, 4));
        rm0 = fmaxf(rm0, __shfl_xor_sync(0xffffffffu, rm0, 2, 4));
        rm1 = fmaxf(rm1, __shfl_xor_sync(0xffffffffu, rm1, 1, 4));
        rm1 = fmaxf(rm1, __shfl_xor_sync(0xffffffffu, rm1, 2, 4));
        float mn0 = fmaxf(m0, rm0), mn1 = fmaxf(m1, rm1);
        float c0 = __expf(m0 - mn0), c1 = __expf(m1 - mn1);
        m0 = mn0; m1 = mn1;
        float ps0 = 0.0f, ps1 = 0.0f;
#pragma unroll
        for (int t = 0; t < 4; t++) {
            s[t][0] = __expf(s[t][0] - mn0); ps0 += s[t][0];
            s[t][1] = __expf(s[t][1] - mn0); ps0 += s[t][1];
            s[t][2] = __expf(s[t][2] - mn1); ps1 += s[t][2];
            s[t][3] = __expf(s[t][3] - mn1); ps1 += s[t][3];
        }
        ps0 += __shfl_xor_sync(0xffffffffu, ps0, 1, 4);
        ps0 += __shfl_xor_sync(0xffffffffu, ps0, 2, 4);
        ps1 += __shfl_xor_sync(0xffffffffu, ps1, 1, 4);
        ps1 += __shfl_xor_sync(0xffffffffu, ps1, 2, 4);
        l0 = l0 * c0 + ps0; l1 = l1 * c1 + ps1;
#pragma unroll
        for (int t = 0; t < 8; t++) {
            o[t][0] *= c0; o[t][1] *= c0; o[t][2] *= c1; o[t][3] *= c1;
        }

        // P accum -> A fragments (2 key-groups of 16)
        uint32_t ph[2][4], pl[2][4];
#pragma unroll
        for (int j = 0; j < 2; j++) {
            split2(s[2*j][0],   s[2*j][1],   ph[j][0], pl[j][0]);
            split2(s[2*j][2],   s[2*j][3],   ph[j][1], pl[j][1]);
            split2(s[2*j+1][0], s[2*j+1][1], ph[j][2], pl[j][2]);
            split2(s[2*j+1][2], s[2*j+1][3], ph[j][3], pl[j][3]);
        }

        // O += P V
#pragma unroll
        for (int j = 0; j < 2; j++) {
#pragma unroll
            for (int np = 0; np < 4; np++) {
                uint32_t vh4[4], vl4[4];
                uint32_t vo = sb + 9216 + vOff + (uint32_t)j * 2304 + (uint32_t)np * 32;
                LDSM4T(vh4, vo);
                LDSM4T(vl4, vo + 4608);
#pragma unroll
                for (int h8 = 0; h8 < 2; h8++) {
                    float* cc = o[np * 2 + h8];
                    mma16816(cc, ph[j], vh4 + h8 * 2);
                    mma16816(cc, pl[j], vh4 + h8 * 2);
                    mma16816(cc, ph[j], vl4 + h8 * 2);
                }
            }
        }
        __syncthreads();
    }

    float i0 = 1.0f / l0, i1 = 1.0f / l1;
    int b = bh >> 4, hh = bh & 15;
    int r0 = q0 + w * 16 + (lane >> 2);
    size_t base0 = ((size_t)(b * 512 + r0) * 1024 + hh * 64 + (lane & 3) * 2) >> 1;
    size_t base1 = ((size_t)(b * 512 + r0 + 8) * 1024 + hh * 64 + (lane & 3) * 2) >> 1;
#pragma unroll
    for (int t = 0; t < 8; t++) {
        uint32_t hi, lo;
        split2(o[t][0] * i0, o[t][1] * i0, hi, lo);
        g_oh[base0 + t * 4] = hi; g_ol[base0 + t * 4] = lo;
        split2(o[t][2] * i1, o[t][3] * i1, hi, lo);
        g_oh[base1 + t * 4] = hi; g_ol[base1 + t * 4] = lo;
    }
}

// ---------------- launch ------------------------------------------------------
extern "C" void kernel_launch(void* const* d_in, const int* in_sizes, int n_in,
                              void* d_out, int out_size) {
    (void)in_sizes; (void)n_in; (void)out_size;
    const float* queries = (const float*)d_in[0];
    const float* keys    = (const float*)d_in[1];
    const float* values  = (const float*)d_in[2];
    const float* boxes   = (const float*)d_in[3];
    const float* bq = (const float*)d_in[5];
    const float* bk = (const float*)d_in[7];
    const float* bv = (const float*)d_in[9];
    const float* bo = (const float*)d_in[11];
    const float* Wq = (const float*)d_in[4];
    const float* Wk = (const float*)d_in[6];
    const float* Wv = (const float*)d_in[8];
    const float* Wo = (const float*)d_in[10];
    const float* Wg = (const float*)d_in[12];
    const float* bg = (const float*)d_in[13];
    float* out = (float*)d_out;

    cudaFuncSetAttribute(fused_gemm_bias_kernel,
                         cudaFuncAttributeMaxDynamicSharedMemorySize, FUSED_SMEM);
    cudaFuncSetAttribute(attn_mma_kernel,
                         cudaFuncAttributeMaxDynamicSharedMemorySize, ATTN_SMEM);

    boxfeat_kernel<<<16, 256>>>(boxes);
    conv_all_kernel<<<16384, 256>>>(queries, keys, values, Wq, Wk, Wv, Wo);
    fused_gemm_bias_kernel<<<8960, 256, FUSED_SMEM>>>(
        bq, bk, bv, nullptr, Wg, bg, /*a_sel=*/0, /*mode=*/1);
    attn_mma_kernel<<<dim3(8, 128), 128, ATTN_SMEM>>>();
    fused_gemm_bias_kernel<<<256, 256, FUSED_SMEM>>>(
        bo, bo, bo, out, Wg, bg, /*a_sel=*/1, /*mode=*/0);
}